// round 8
// baseline (speedup 1.0000x reference)
#include <cuda_runtime.h>
#include <cuda_fp16.h>
#include <math.h>
#include <stdint.h>

#define N 4096
#define D 2048
#define MARGIN 0.3f

// ---------------------------------------------------------------------------
// Device globals (no allocation allowed)
// ---------------------------------------------------------------------------
__device__ __half g_Hf[(size_t)N * D];   // fp16-rounded copy of features
__device__ float g_sq[N];
__device__ int   g_lab[N];
__device__ float g_ap[N];
__device__ float g_an[N];

// ---------------------------------------------------------------------------
// Kernel 1: round fp32 -> fp16 copy, squared norms (fp32), init accumulators
// ---------------------------------------------------------------------------
__global__ void prep_kernel(const float* __restrict__ F,
                            const int* __restrict__ lab) {
    int row = blockIdx.x;
    const float4* f4 = reinterpret_cast<const float4*>(F + (size_t)row * D);
    __half2* h2 = reinterpret_cast<__half2*>(g_Hf + (size_t)row * D);
    float s = 0.f;
    for (int k = threadIdx.x; k < D / 4; k += blockDim.x) {
        float4 v = f4[k];
        s += v.x * v.x + v.y * v.y + v.z * v.z + v.w * v.w;
        h2[k * 2 + 0] = __floats2half2_rn(v.x, v.y);
        h2[k * 2 + 1] = __floats2half2_rn(v.z, v.w);
    }
    __shared__ float red[8];
    #pragma unroll
    for (int o = 16; o; o >>= 1) s += __shfl_xor_sync(0xffffffffu, s, o);
    if ((threadIdx.x & 31) == 0) red[threadIdx.x >> 5] = s;
    __syncthreads();
    if (threadIdx.x == 0) {
        float t = 0.f;
        #pragma unroll
        for (int w = 0; w < 8; w++) t += red[w];
        g_sq[row]  = t;
        g_lab[row] = lab[row];
        g_ap[row]  = 0.f;
        g_an[row]  = __int_as_float(0x7f800000);
    }
}

// ---------------------------------------------------------------------------
// Kernel 2: fp16 mma.sync Gram tile 128x256, triangular cover, 3-stage pipe.
// 8 warps, each 64x64. Every tile mines rows AND cols (overlap harmless).
// ---------------------------------------------------------------------------
#define TM 128
#define TN 256
#define KCH 64                       // fp16 per K chunk (=128B/row)
#define NCHUNK (D / KCH)             // 32
#define ROWB 144                     // padded row bytes
#define A_BYTES (TM * ROWB)          // 18432
#define B_BYTES (TN * ROWB)          // 36864
#define STAGEB (A_BYTES + B_BYTES)   // 55296
#define NSTAGE 3
#define NBLK 272                     // sum_{bi=0}^{31} (bi+2)>>1

#define OFF_RSQ (NSTAGE * STAGEB)          // float[128]
#define OFF_RLB (OFF_RSQ + 512)            // int[128]
#define OFF_CSQ (OFF_RLB + 512)            // float[256]
#define OFF_CLB (OFF_CSQ + 1024)           // int[256]
#define SMEM_BYTES (OFF_CLB + 1024)

__device__ __forceinline__ uint32_t smem_u32(const void* p) {
    uint32_t a;
    asm("{ .reg .u64 t; cvta.to.shared.u64 t, %1; cvt.u32.u64 %0, t; }" : "=r"(a) : "l"(p));
    return a;
}
__device__ __forceinline__ void cp16(uint32_t dst, const void* src) {
    asm volatile("cp.async.cg.shared.global [%0], [%1], 16;" :: "r"(dst), "l"(src));
}
__device__ __forceinline__ void cp_commit() {
    asm volatile("cp.async.commit_group;" ::: "memory");
}
__device__ __forceinline__ void ldsm_x4(uint32_t& r0, uint32_t& r1, uint32_t& r2,
                                        uint32_t& r3, uint32_t addr) {
    asm volatile("ldmatrix.sync.aligned.m8n8.x4.shared.b16 {%0,%1,%2,%3}, [%4];"
                 : "=r"(r0), "=r"(r1), "=r"(r2), "=r"(r3) : "r"(addr));
}
__device__ __forceinline__ void mma_f16(float* c, uint32_t a0, uint32_t a1,
                                        uint32_t a2, uint32_t a3,
                                        uint32_t b0, uint32_t b1) {
    asm volatile("mma.sync.aligned.m16n8k16.row.col.f32.f16.f16.f32 "
                 "{%0,%1,%2,%3}, {%4,%5,%6,%7}, {%8,%9}, {%0,%1,%2,%3};"
                 : "+f"(c[0]), "+f"(c[1]), "+f"(c[2]), "+f"(c[3])
                 : "r"(a0), "r"(a1), "r"(a2), "r"(a3), "r"(b0), "r"(b1));
}

__global__ __launch_bounds__(256, 1)
void mma_mine_kernel() {
    extern __shared__ char sb[];
    const uint32_t sbase = smem_u32(sb);
    const int tid  = threadIdx.x;
    const int lane = tid & 31;
    const int wid  = tid >> 5;
    const int wm   = wid >> 2;        // 0..1  (64 rows each)
    const int wn   = wid & 3;         // 0..3  (64 cols each)

    // decode (bi, bjj): row-tile bi has (bi+2)>>1 col-tiles of 256
    int t = blockIdx.x;
    int bi = 0, s = 0;
    while (s + ((bi + 2) >> 1) <= t) { s += (bi + 2) >> 1; bi++; }
    int bjj = t - s;

    const int rowBase = bi * TM;
    const int colBase = bjj * TN;

    // stage row/col sq + labels
    if (tid < 128) {
        ((float*)(sb + OFF_RSQ))[tid] = g_sq[rowBase + tid];
        ((int*)(sb + OFF_RLB))[tid]   = g_lab[rowBase + tid];
    }
    ((float*)(sb + OFF_CSQ))[tid] = g_sq[colBase + tid];
    ((int*)(sb + OFF_CLB))[tid]   = g_lab[colBase + tid];

    // cp.async mapping: A 1024 vecs (4/thread), B 2048 vecs (8/thread)
    const int ldR = tid >> 3;         // 0..31 (+32*i)
    const int ldQ = tid & 7;          // 16B slot in 128B row

    auto issue = [&](int c) {
        const int kc = c * KCH;
        const uint32_t st = sbase + (c % NSTAGE) * STAGEB;
        const uint32_t aB = st;
        const uint32_t bB = st + A_BYTES;
        #pragma unroll
        for (int i = 0; i < 4; i++) {
            int r = ldR + i * 32;
            cp16(aB + r * ROWB + ldQ * 16,
                 g_Hf + (size_t)(rowBase + r) * D + kc + ldQ * 8);
        }
        #pragma unroll
        for (int i = 0; i < 8; i++) {
            int r = ldR + i * 32;
            cp16(bB + r * ROWB + ldQ * 16,
                 g_Hf + (size_t)(colBase + r) * D + kc + ldQ * 8);
        }
        cp_commit();
    };

    // ldmatrix offsets within a stage
    uint32_t aOff[4];
    #pragma unroll
    for (int mi = 0; mi < 4; mi++) {
        int r = wm * 64 + mi * 16 + (lane & 15);
        aOff[mi] = r * ROWB + (lane >> 4) * 16;
    }
    uint32_t bOff[4];
    {
        int mat = lane >> 3;
        #pragma unroll
        for (int nt = 0; nt < 4; nt++) {
            int n = wn * 64 + nt * 16 + ((mat & 2) << 2) + (lane & 7);
            bOff[nt] = A_BYTES + n * ROWB + (mat & 1) * 16;
        }
    }

    float acc[4][8][4];
    #pragma unroll
    for (int mi = 0; mi < 4; mi++)
        #pragma unroll
        for (int ni = 0; ni < 8; ni++)
            #pragma unroll
            for (int r = 0; r < 4; r++) acc[mi][ni][r] = 0.f;

    issue(0); issue(1); issue(2);

    for (int c = 0; c < NCHUNK; c++) {
        int ahead = NCHUNK - 1 - c;
        if (ahead >= 2)      asm volatile("cp.async.wait_group 2;" ::: "memory");
        else if (ahead == 1) asm volatile("cp.async.wait_group 1;" ::: "memory");
        else                 asm volatile("cp.async.wait_group 0;" ::: "memory");
        __syncthreads();

        const uint32_t st = sbase + (c % NSTAGE) * STAGEB;
        #pragma unroll
        for (int ks = 0; ks < 4; ks++) {   // 4 x k16 = 64 k per chunk
            uint32_t a[4][4];
            #pragma unroll
            for (int mi = 0; mi < 4; mi++)
                ldsm_x4(a[mi][0], a[mi][1], a[mi][2], a[mi][3],
                        st + aOff[mi] + ks * 32);
            uint32_t b[8][2];
            #pragma unroll
            for (int nt = 0; nt < 4; nt++) {
                uint32_t r0, r1, r2, r3;
                ldsm_x4(r0, r1, r2, r3, st + bOff[nt] + ks * 32);
                b[nt * 2 + 0][0] = r0; b[nt * 2 + 0][1] = r1;
                b[nt * 2 + 1][0] = r2; b[nt * 2 + 1][1] = r3;
            }
            #pragma unroll
            for (int mi = 0; mi < 4; mi++)
                #pragma unroll
                for (int ni = 0; ni < 8; ni++)
                    mma_f16(acc[mi][ni], a[mi][0], a[mi][1], a[mi][2], a[mi][3],
                            b[ni][0], b[ni][1]);
        }
        __syncthreads();
        if (c + NSTAGE < NCHUNK) issue(c + NSTAGE);
    }

    // ------------------- epilogue: distance + two-way mining -------------------
    const float* rsq = (const float*)(sb + OFF_RSQ);
    const int*   rlb = (const int*)(sb + OFF_RLB);
    const float* csq = (const float*)(sb + OFF_CSQ);
    const int*   clb = (const int*)(sb + OFF_CLB);

    const float INF = __int_as_float(0x7f800000);

    float apv[4][2], anv[4][2];
    float sqr[4][2]; int lbr[4][2];
    #pragma unroll
    for (int mi = 0; mi < 4; mi++)
        #pragma unroll
        for (int h = 0; h < 2; h++) {
            apv[mi][h] = 0.f;
            anv[mi][h] = INF;
            int r = wm * 64 + mi * 16 + h * 8 + (lane >> 2);
            sqr[mi][h] = rsq[r];
            lbr[mi][h] = rlb[r];
        }

    #pragma unroll
    for (int ni = 0; ni < 8; ni++) {
        const int jl = wn * 64 + ni * 8 + (lane & 3) * 2;
        float cap[2] = {0.f, 0.f};
        float can[2] = {INF, INF};
        #pragma unroll
        for (int e = 0; e < 2; e++) {
            const float sqj = csq[jl + e];
            const int   lj  = clb[jl + e];
            #pragma unroll
            for (int mi = 0; mi < 4; mi++)
                #pragma unroll
                for (int h = 0; h < 2; h++) {
                    float g = acc[mi][ni][h * 2 + e];
                    float d2 = fmaf(-2.f, g, sqr[mi][h] + sqj);
                    float dist = d2 > 0.f ? sqrtf(d2) : 0.f;
                    if (lbr[mi][h] == lj) {
                        apv[mi][h] = fmaxf(apv[mi][h], dist);
                        cap[e] = fmaxf(cap[e], dist);
                    } else {
                        anv[mi][h] = fminf(anv[mi][h], dist);
                        can[e] = fminf(can[e], dist);
                    }
                }
        }
        // column mining: reduce over lane>>2 groups (covers all 64 rows of warp)
        #pragma unroll
        for (int e = 0; e < 2; e++) {
            #pragma unroll
            for (int o = 4; o <= 16; o <<= 1) {
                cap[e] = fmaxf(cap[e], __shfl_xor_sync(0xffffffffu, cap[e], o));
                can[e] = fminf(can[e], __shfl_xor_sync(0xffffffffu, can[e], o));
            }
            if (lane < 4) {
                int col = colBase + wn * 64 + ni * 8 + lane * 2 + e;
                atomicMax((int*)&g_ap[col], __float_as_int(cap[e]));
                atomicMin((int*)&g_an[col], __float_as_int(can[e]));
            }
        }
    }

    // row-side reduction over 4 lanes sharing each row
    #pragma unroll
    for (int mi = 0; mi < 4; mi++)
        #pragma unroll
        for (int h = 0; h < 2; h++) {
            #pragma unroll
            for (int o = 1; o <= 2; o <<= 1) {
                apv[mi][h] = fmaxf(apv[mi][h], __shfl_xor_sync(0xffffffffu, apv[mi][h], o));
                anv[mi][h] = fminf(anv[mi][h], __shfl_xor_sync(0xffffffffu, anv[mi][h], o));
            }
        }
    if ((lane & 3) == 0) {
        #pragma unroll
        for (int mi = 0; mi < 4; mi++)
            #pragma unroll
            for (int h = 0; h < 2; h++) {
                int row = rowBase + wm * 64 + mi * 16 + h * 8 + (lane >> 2);
                atomicMax((int*)&g_ap[row], __float_as_int(apv[mi][h]));
                atomicMin((int*)&g_an[row], __float_as_int(anv[mi][h]));
            }
    }
}

// ---------------------------------------------------------------------------
// Kernel 3: final scalar loss
// ---------------------------------------------------------------------------
__global__ void loss_kernel(float* __restrict__ out) {
    __shared__ float ssum[256];
    __shared__ int   scnt[256];
    float s = 0.f; int c = 0;
    for (int i = threadIdx.x; i < N; i += 256) {
        float ap = g_ap[i];
        float an = g_an[i];
        if (ap > 0.f && isfinite(an)) {
            c++;
            float v = ap - an + MARGIN;
            s += v > 0.f ? v : 0.f;
        }
    }
    ssum[threadIdx.x] = s;
    scnt[threadIdx.x] = c;
    __syncthreads();
    for (int o = 128; o; o >>= 1) {
        if (threadIdx.x < o) {
            ssum[threadIdx.x] += ssum[threadIdx.x + o];
            scnt[threadIdx.x] += scnt[threadIdx.x + o];
        }
        __syncthreads();
    }
    if (threadIdx.x == 0) {
        int n = scnt[0];
        out[0] = (n > 0) ? (ssum[0] / (float)n) : 0.f;
    }
}

// ---------------------------------------------------------------------------
extern "C" void kernel_launch(void* const* d_in, const int* in_sizes, int n_in,
                              void* d_out, int out_size) {
    const float* F   = (const float*)d_in[0];
    const int*   lab = (const int*)d_in[1];
    float* out = (float*)d_out;

    cudaFuncSetAttribute(mma_mine_kernel,
                         cudaFuncAttributeMaxDynamicSharedMemorySize, SMEM_BYTES);

    prep_kernel<<<N, 256>>>(F, lab);
    mma_mine_kernel<<<NBLK, 256, SMEM_BYTES>>>();
    loss_kernel<<<1, 256>>>(out);
}

// round 9
// speedup vs baseline: 1.0600x; 1.0600x over previous
#include <cuda_runtime.h>
#include <cuda_fp16.h>
#include <math.h>
#include <stdint.h>

#define N 4096
#define D 2048
#define MARGIN 0.3f

// ---------------------------------------------------------------------------
// Device globals (no allocation allowed)
// ---------------------------------------------------------------------------
__device__ __half g_Hf[(size_t)N * D];   // fp16-rounded copy of features
__device__ float g_sq[N];
__device__ int   g_lab[N];
__device__ float g_ap[N];
__device__ float g_an[N];

// ---------------------------------------------------------------------------
// Kernel 1: round fp32 -> fp16 copy, squared norms (fp32), init accumulators
// ---------------------------------------------------------------------------
__global__ void prep_kernel(const float* __restrict__ F,
                            const int* __restrict__ lab) {
    int row = blockIdx.x;
    const float4* f4 = reinterpret_cast<const float4*>(F + (size_t)row * D);
    __half2* h2 = reinterpret_cast<__half2*>(g_Hf + (size_t)row * D);
    float s = 0.f;
    for (int k = threadIdx.x; k < D / 4; k += blockDim.x) {
        float4 v = f4[k];
        s += v.x * v.x + v.y * v.y + v.z * v.z + v.w * v.w;
        h2[k * 2 + 0] = __floats2half2_rn(v.x, v.y);
        h2[k * 2 + 1] = __floats2half2_rn(v.z, v.w);
    }
    __shared__ float red[8];
    #pragma unroll
    for (int o = 16; o; o >>= 1) s += __shfl_xor_sync(0xffffffffu, s, o);
    if ((threadIdx.x & 31) == 0) red[threadIdx.x >> 5] = s;
    __syncthreads();
    if (threadIdx.x == 0) {
        float t = 0.f;
        #pragma unroll
        for (int w = 0; w < 8; w++) t += red[w];
        g_sq[row]  = t;
        g_lab[row] = lab[row];
        g_ap[row]  = 0.f;
        g_an[row]  = __int_as_float(0x7f800000);
    }
}

// ---------------------------------------------------------------------------
// Kernel 2: fp16 mma.sync Gram tile (128x128), LOWER TRIANGLE ONLY,
// 3-stage cp.async pipeline at occupancy 2. Off-diagonal tiles mine both ways.
// ---------------------------------------------------------------------------
#define TM 128
#define TN 128
#define KCH 64                       // fp16 elements per K chunk (=128B/row)
#define NCHUNK (D / KCH)             // 32
#define ROWB 144                     // padded row bytes (128 data + 16 pad)
#define TILEB (TM * ROWB)            // 18432 per tile
#define STAGEB (2 * TILEB)           // A + B per stage = 36864
#define NSTAGE 3
#define NTILE (N / TM)               // 32
#define NBLK (NTILE * (NTILE + 1) / 2)  // 528

#define OFF_RSQ (NSTAGE * STAGEB)    // float[128]
#define OFF_RLB (OFF_RSQ + 512)     // int[128]
#define OFF_CSQ (OFF_RLB + 512)     // float[128]
#define OFF_CLB (OFF_CSQ + 512)     // int[128]
#define SMEM_BYTES (OFF_CLB + 512)   // 112640

__device__ __forceinline__ uint32_t smem_u32(const void* p) {
    uint32_t a;
    asm("{ .reg .u64 t; cvta.to.shared.u64 t, %1; cvt.u32.u64 %0, t; }" : "=r"(a) : "l"(p));
    return a;
}
__device__ __forceinline__ void cp16(uint32_t dst, const void* src) {
    asm volatile("cp.async.cg.shared.global [%0], [%1], 16;" :: "r"(dst), "l"(src));
}
__device__ __forceinline__ void cp_commit() {
    asm volatile("cp.async.commit_group;" ::: "memory");
}
__device__ __forceinline__ void ldsm_x4(uint32_t& r0, uint32_t& r1, uint32_t& r2,
                                        uint32_t& r3, uint32_t addr) {
    asm volatile("ldmatrix.sync.aligned.m8n8.x4.shared.b16 {%0,%1,%2,%3}, [%4];"
                 : "=r"(r0), "=r"(r1), "=r"(r2), "=r"(r3) : "r"(addr));
}
__device__ __forceinline__ void mma_f16(float* c, uint32_t a0, uint32_t a1,
                                        uint32_t a2, uint32_t a3,
                                        uint32_t b0, uint32_t b1) {
    asm volatile("mma.sync.aligned.m16n8k16.row.col.f32.f16.f16.f32 "
                 "{%0,%1,%2,%3}, {%4,%5,%6,%7}, {%8,%9}, {%0,%1,%2,%3};"
                 : "+f"(c[0]), "+f"(c[1]), "+f"(c[2]), "+f"(c[3])
                 : "r"(a0), "r"(a1), "r"(a2), "r"(a3), "r"(b0), "r"(b1));
}

__global__ __launch_bounds__(256, 2)
void mma_mine_kernel() {
    extern __shared__ char sb[];
    const uint32_t sbase = smem_u32(sb);
    const int tid  = threadIdx.x;
    const int lane = tid & 31;
    const int wid  = tid >> 5;
    const int wm   = wid >> 1;        // 0..3  (32 rows each)
    const int wn   = wid & 1;         // 0..1  (64 cols each)

    // decode lower-triangular tile index: bi >= bj
    int t = blockIdx.x;
    int bi = (int)floorf((sqrtf(8.0f * (float)t + 1.0f) - 1.0f) * 0.5f);
    while ((bi + 1) * (bi + 2) / 2 <= t) ++bi;
    while (bi * (bi + 1) / 2 > t) --bi;
    int bj = t - bi * (bi + 1) / 2;

    const int rowBase = bi * TM;
    const int colBase = bj * TN;
    const bool offdiag = (bi != bj);

    // stage row/col sq + labels
    if (tid < 128) {
        ((float*)(sb + OFF_RSQ))[tid] = g_sq[rowBase + tid];
        ((int*)(sb + OFF_RLB))[tid]   = g_lab[rowBase + tid];
        ((float*)(sb + OFF_CSQ))[tid] = g_sq[colBase + tid];
        ((int*)(sb + OFF_CLB))[tid]   = g_lab[colBase + tid];
    }

    // cp.async load mapping: 1024 16B vectors per tile, 4 per thread
    const int ldR = tid >> 3;         // row (with +32*i)
    const int ldQ = tid & 7;          // 16B slot within 128B row

    auto issue = [&](int c) {
        const int kc = c * KCH;
        const uint32_t st = sbase + (c % NSTAGE) * STAGEB;
        const uint32_t aB = st;
        const uint32_t bB = st + TILEB;
        #pragma unroll
        for (int i = 0; i < 4; i++) {
            int r = ldR + i * 32;
            cp16(aB + r * ROWB + ldQ * 16,
                 g_Hf + (size_t)(rowBase + r) * D + kc + ldQ * 8);
            cp16(bB + r * ROWB + ldQ * 16,
                 g_Hf + (size_t)(colBase + r) * D + kc + ldQ * 8);
        }
        cp_commit();
    };

    // ldmatrix offsets within a stage
    uint32_t aOff[2];
    #pragma unroll
    for (int mi = 0; mi < 2; mi++) {
        int r = wm * 32 + mi * 16 + (lane & 15);
        aOff[mi] = r * ROWB + (lane >> 4) * 16;
    }
    uint32_t bOff[4];
    {
        int mat = lane >> 3;
        #pragma unroll
        for (int nt = 0; nt < 4; nt++) {
            int n = wn * 64 + nt * 16 + ((mat & 2) << 2) + (lane & 7);
            bOff[nt] = TILEB + n * ROWB + (mat & 1) * 16;
        }
    }

    float acc[2][8][4];
    #pragma unroll
    for (int mi = 0; mi < 2; mi++)
        #pragma unroll
        for (int ni = 0; ni < 8; ni++)
            #pragma unroll
            for (int r = 0; r < 4; r++) acc[mi][ni][r] = 0.f;

    issue(0); issue(1); issue(2);

    for (int c = 0; c < NCHUNK; c++) {
        int ahead = NCHUNK - 1 - c;
        if (ahead >= 2)      asm volatile("cp.async.wait_group 2;" ::: "memory");
        else if (ahead == 1) asm volatile("cp.async.wait_group 1;" ::: "memory");
        else                 asm volatile("cp.async.wait_group 0;" ::: "memory");
        __syncthreads();

        const uint32_t st = sbase + (c % NSTAGE) * STAGEB;
        #pragma unroll
        for (int ks = 0; ks < 4; ks++) {   // 4 x k16 = 64 k per chunk
            uint32_t a[2][4];
            #pragma unroll
            for (int mi = 0; mi < 2; mi++)
                ldsm_x4(a[mi][0], a[mi][1], a[mi][2], a[mi][3],
                        st + aOff[mi] + ks * 32);
            uint32_t b[8][2];
            #pragma unroll
            for (int nt = 0; nt < 4; nt++) {
                uint32_t r0, r1, r2, r3;
                ldsm_x4(r0, r1, r2, r3, st + bOff[nt] + ks * 32);
                b[nt * 2 + 0][0] = r0; b[nt * 2 + 0][1] = r1;
                b[nt * 2 + 1][0] = r2; b[nt * 2 + 1][1] = r3;
            }
            #pragma unroll
            for (int mi = 0; mi < 2; mi++)
                #pragma unroll
                for (int ni = 0; ni < 8; ni++)
                    mma_f16(acc[mi][ni], a[mi][0], a[mi][1], a[mi][2], a[mi][3],
                            b[ni][0], b[ni][1]);
        }
        __syncthreads();
        if (c + NSTAGE < NCHUNK) issue(c + NSTAGE);
    }

    // ------------------- epilogue: distance + two-way mining -------------------
    const float* rsq = (const float*)(sb + OFF_RSQ);
    const int*   rlb = (const int*)(sb + OFF_RLB);
    const float* csq = (const float*)(sb + OFF_CSQ);
    const int*   clb = (const int*)(sb + OFF_CLB);

    const float INF = __int_as_float(0x7f800000);

    float apv[2][2], anv[2][2];
    float sqr[2][2]; int lbr[2][2];
    #pragma unroll
    for (int mi = 0; mi < 2; mi++)
        #pragma unroll
        for (int h = 0; h < 2; h++) {
            apv[mi][h] = 0.f;
            anv[mi][h] = INF;
            int r = wm * 32 + mi * 16 + h * 8 + (lane >> 2);
            sqr[mi][h] = rsq[r];
            lbr[mi][h] = rlb[r];
        }

    #pragma unroll
    for (int ni = 0; ni < 8; ni++) {
        const int jl = wn * 64 + ni * 8 + (lane & 3) * 2;
        float cap[2] = {0.f, 0.f};
        float can[2] = {INF, INF};
        #pragma unroll
        for (int e = 0; e < 2; e++) {
            const float sqj = csq[jl + e];
            const int   lj  = clb[jl + e];
            #pragma unroll
            for (int mi = 0; mi < 2; mi++)
                #pragma unroll
                for (int h = 0; h < 2; h++) {
                    float g = acc[mi][ni][h * 2 + e];
                    float d2 = fmaf(-2.f, g, sqr[mi][h] + sqj);
                    float dist = d2 > 0.f ? sqrtf(d2) : 0.f;
                    if (lbr[mi][h] == lj) {
                        apv[mi][h] = fmaxf(apv[mi][h], dist);
                        cap[e] = fmaxf(cap[e], dist);
                    } else {
                        anv[mi][h] = fminf(anv[mi][h], dist);
                        can[e] = fminf(can[e], dist);
                    }
                }
        }
        if (offdiag) {
            // column mining: reduce over lane>>2 groups (same lane&3 = same col)
            #pragma unroll
            for (int e = 0; e < 2; e++) {
                #pragma unroll
                for (int o = 4; o <= 16; o <<= 1) {
                    cap[e] = fmaxf(cap[e], __shfl_xor_sync(0xffffffffu, cap[e], o));
                    can[e] = fminf(can[e], __shfl_xor_sync(0xffffffffu, can[e], o));
                }
                if (lane < 4) {
                    int col = colBase + wn * 64 + ni * 8 + lane * 2 + e;
                    atomicMax((int*)&g_ap[col], __float_as_int(cap[e]));
                    atomicMin((int*)&g_an[col], __float_as_int(can[e]));
                }
            }
        }
    }

    // row-side reduction over 4 lanes sharing each row
    #pragma unroll
    for (int mi = 0; mi < 2; mi++)
        #pragma unroll
        for (int h = 0; h < 2; h++) {
            #pragma unroll
            for (int o = 1; o <= 2; o <<= 1) {
                apv[mi][h] = fmaxf(apv[mi][h], __shfl_xor_sync(0xffffffffu, apv[mi][h], o));
                anv[mi][h] = fminf(anv[mi][h], __shfl_xor_sync(0xffffffffu, anv[mi][h], o));
            }
        }
    if ((lane & 3) == 0) {
        #pragma unroll
        for (int mi = 0; mi < 2; mi++)
            #pragma unroll
            for (int h = 0; h < 2; h++) {
                int row = rowBase + wm * 32 + mi * 16 + h * 8 + (lane >> 2);
                atomicMax((int*)&g_ap[row], __float_as_int(apv[mi][h]));
                atomicMin((int*)&g_an[row], __float_as_int(anv[mi][h]));
            }
    }
}

// ---------------------------------------------------------------------------
// Kernel 3: final scalar loss
// ---------------------------------------------------------------------------
__global__ void loss_kernel(float* __restrict__ out) {
    __shared__ float ssum[256];
    __shared__ int   scnt[256];
    float s = 0.f; int c = 0;
    for (int i = threadIdx.x; i < N; i += 256) {
        float ap = g_ap[i];
        float an = g_an[i];
        if (ap > 0.f && isfinite(an)) {
            c++;
            float v = ap - an + MARGIN;
            s += v > 0.f ? v : 0.f;
        }
    }
    ssum[threadIdx.x] = s;
    scnt[threadIdx.x] = c;
    __syncthreads();
    for (int o = 128; o; o >>= 1) {
        if (threadIdx.x < o) {
            ssum[threadIdx.x] += ssum[threadIdx.x + o];
            scnt[threadIdx.x] += scnt[threadIdx.x + o];
        }
        __syncthreads();
    }
    if (threadIdx.x == 0) {
        int n = scnt[0];
        out[0] = (n > 0) ? (ssum[0] / (float)n) : 0.f;
    }
}

// ---------------------------------------------------------------------------
extern "C" void kernel_launch(void* const* d_in, const int* in_sizes, int n_in,
                              void* d_out, int out_size) {
    const float* F   = (const float*)d_in[0];
    const int*   lab = (const int*)d_in[1];
    float* out = (float*)d_out;

    cudaFuncSetAttribute(mma_mine_kernel,
                         cudaFuncAttributeMaxDynamicSharedMemorySize, SMEM_BYTES);

    prep_kernel<<<N, 256>>>(F, lab);
    mma_mine_kernel<<<NBLK, 256, SMEM_BYTES>>>();
    loss_kernel<<<1, 256>>>(out);
}

// round 10
// speedup vs baseline: 1.0753x; 1.0145x over previous
#include <cuda_runtime.h>
#include <cuda_fp16.h>
#include <math.h>
#include <stdint.h>

#define N 4096
#define D 2048
#define MARGIN 0.3f

// ---------------------------------------------------------------------------
// Device globals (no allocation allowed)
// ---------------------------------------------------------------------------
__device__ __half g_Hf[(size_t)N * D];   // fp16-rounded copy of features
__device__ float g_sq[N];
__device__ int   g_lab[N];
__device__ float g_ap[N];
__device__ float g_an[N];
__device__ unsigned g_done;              // finished-CTA ticket

// ---------------------------------------------------------------------------
// Kernel 1: round fp32 -> fp16 copy, squared norms (fp32), init accumulators
// ---------------------------------------------------------------------------
__global__ void prep_kernel(const float* __restrict__ F,
                            const int* __restrict__ lab) {
    int row = blockIdx.x;
    const float4* f4 = reinterpret_cast<const float4*>(F + (size_t)row * D);
    __half2* h2 = reinterpret_cast<__half2*>(g_Hf + (size_t)row * D);
    float s = 0.f;
    for (int k = threadIdx.x; k < D / 4; k += blockDim.x) {
        float4 v = f4[k];
        s += v.x * v.x + v.y * v.y + v.z * v.z + v.w * v.w;
        h2[k * 2 + 0] = __floats2half2_rn(v.x, v.y);
        h2[k * 2 + 1] = __floats2half2_rn(v.z, v.w);
    }
    __shared__ float red[8];
    #pragma unroll
    for (int o = 16; o; o >>= 1) s += __shfl_xor_sync(0xffffffffu, s, o);
    if ((threadIdx.x & 31) == 0) red[threadIdx.x >> 5] = s;
    __syncthreads();
    if (threadIdx.x == 0) {
        float t = 0.f;
        #pragma unroll
        for (int w = 0; w < 8; w++) t += red[w];
        g_sq[row]  = t;
        g_lab[row] = lab[row];
        g_ap[row]  = 0.f;
        g_an[row]  = __int_as_float(0x7f800000);
        if (row == 0) g_done = 0;
    }
}

// ---------------------------------------------------------------------------
// Kernel 2: fp16 mma.sync Gram tile (128x128), LOWER TRIANGLE ONLY.
// 3-stage cp.async pipeline, ONE barrier per chunk. Two-way mining.
// Last CTA to finish computes the final scalar loss (fused loss kernel).
// ---------------------------------------------------------------------------
#define TM 128
#define TN 128
#define KCH 64                       // fp16 elements per K chunk (=128B/row)
#define NCHUNK (D / KCH)             // 32
#define ROWB 144                     // padded row bytes (128 data + 16 pad)
#define TILEB (TM * ROWB)            // 18432 per tile
#define STAGEB (2 * TILEB)           // A + B per stage = 36864
#define NSTAGE 3
#define NTILE (N / TM)               // 32
#define NBLK (NTILE * (NTILE + 1) / 2)  // 528

#define OFF_RSQ (NSTAGE * STAGEB)    // float[128]
#define OFF_RLB (OFF_RSQ + 512)     // int[128]
#define OFF_CSQ (OFF_RLB + 512)     // float[128]
#define OFF_CLB (OFF_CSQ + 512)     // int[128]
#define SMEM_BYTES (OFF_CLB + 512)

__device__ __forceinline__ uint32_t smem_u32(const void* p) {
    uint32_t a;
    asm("{ .reg .u64 t; cvta.to.shared.u64 t, %1; cvt.u32.u64 %0, t; }" : "=r"(a) : "l"(p));
    return a;
}
__device__ __forceinline__ void cp16(uint32_t dst, const void* src) {
    asm volatile("cp.async.cg.shared.global [%0], [%1], 16;" :: "r"(dst), "l"(src));
}
__device__ __forceinline__ void cp_commit() {
    asm volatile("cp.async.commit_group;" ::: "memory");
}
__device__ __forceinline__ void ldsm_x4(uint32_t& r0, uint32_t& r1, uint32_t& r2,
                                        uint32_t& r3, uint32_t addr) {
    asm volatile("ldmatrix.sync.aligned.m8n8.x4.shared.b16 {%0,%1,%2,%3}, [%4];"
                 : "=r"(r0), "=r"(r1), "=r"(r2), "=r"(r3) : "r"(addr));
}
__device__ __forceinline__ void mma_f16(float* c, uint32_t a0, uint32_t a1,
                                        uint32_t a2, uint32_t a3,
                                        uint32_t b0, uint32_t b1) {
    asm volatile("mma.sync.aligned.m16n8k16.row.col.f32.f16.f16.f32 "
                 "{%0,%1,%2,%3}, {%4,%5,%6,%7}, {%8,%9}, {%0,%1,%2,%3};"
                 : "+f"(c[0]), "+f"(c[1]), "+f"(c[2]), "+f"(c[3])
                 : "r"(a0), "r"(a1), "r"(a2), "r"(a3), "r"(b0), "r"(b1));
}

__global__ __launch_bounds__(256, 2)
void mma_mine_kernel(float* __restrict__ out) {
    extern __shared__ char sb[];
    const uint32_t sbase = smem_u32(sb);
    const int tid  = threadIdx.x;
    const int lane = tid & 31;
    const int wid  = tid >> 5;
    const int wm   = wid >> 1;        // 0..3  (32 rows each)
    const int wn   = wid & 1;         // 0..1  (64 cols each)

    // decode lower-triangular tile index: bi >= bj
    int t = blockIdx.x;
    int bi = (int)floorf((sqrtf(8.0f * (float)t + 1.0f) - 1.0f) * 0.5f);
    while ((bi + 1) * (bi + 2) / 2 <= t) ++bi;
    while (bi * (bi + 1) / 2 > t) --bi;
    int bj = t - bi * (bi + 1) / 2;

    const int rowBase = bi * TM;
    const int colBase = bj * TN;
    const bool offdiag = (bi != bj);

    // stage row/col sq + labels
    if (tid < 128) {
        ((float*)(sb + OFF_RSQ))[tid] = g_sq[rowBase + tid];
        ((int*)(sb + OFF_RLB))[tid]   = g_lab[rowBase + tid];
        ((float*)(sb + OFF_CSQ))[tid] = g_sq[colBase + tid];
        ((int*)(sb + OFF_CLB))[tid]   = g_lab[colBase + tid];
    }

    // cp.async load mapping: 1024 16B vectors per tile, 4 per thread
    const int ldR = tid >> 3;         // row (with +32*i)
    const int ldQ = tid & 7;          // 16B slot within 128B row

    auto issue = [&](int c) {
        const int kc = c * KCH;
        const uint32_t st = sbase + (c % NSTAGE) * STAGEB;
        const uint32_t aB = st;
        const uint32_t bB = st + TILEB;
        #pragma unroll
        for (int i = 0; i < 4; i++) {
            int r = ldR + i * 32;
            cp16(aB + r * ROWB + ldQ * 16,
                 g_Hf + (size_t)(rowBase + r) * D + kc + ldQ * 8);
            cp16(bB + r * ROWB + ldQ * 16,
                 g_Hf + (size_t)(colBase + r) * D + kc + ldQ * 8);
        }
        cp_commit();
    };

    // ldmatrix offsets within a stage
    uint32_t aOff[2];
    #pragma unroll
    for (int mi = 0; mi < 2; mi++) {
        int r = wm * 32 + mi * 16 + (lane & 15);
        aOff[mi] = r * ROWB + (lane >> 4) * 16;
    }
    uint32_t bOff[4];
    {
        int mat = lane >> 3;
        #pragma unroll
        for (int nt = 0; nt < 4; nt++) {
            int n = wn * 64 + nt * 16 + ((mat & 2) << 2) + (lane & 7);
            bOff[nt] = TILEB + n * ROWB + (mat & 1) * 16;
        }
    }

    float acc[2][8][4];
    #pragma unroll
    for (int mi = 0; mi < 2; mi++)
        #pragma unroll
        for (int ni = 0; ni < 8; ni++)
            #pragma unroll
            for (int r = 0; r < 4; r++) acc[mi][ni][r] = 0.f;

    issue(0); issue(1);

    for (int c = 0; c < NCHUNK; c++) {
        // stage c ready? (keep at most 1 younger group in flight)
        if (c == NCHUNK - 1) asm volatile("cp.async.wait_group 0;" ::: "memory");
        else                 asm volatile("cp.async.wait_group 1;" ::: "memory");
        __syncthreads();
        // stage (c+2)%3 == (c-1)%3 is free after this barrier: refill it now
        if (c + 2 < NCHUNK) issue(c + 2);

        const uint32_t st = sbase + (c % NSTAGE) * STAGEB;
        #pragma unroll
        for (int ks = 0; ks < 4; ks++) {   // 4 x k16 = 64 k per chunk
            uint32_t a[2][4];
            #pragma unroll
            for (int mi = 0; mi < 2; mi++)
                ldsm_x4(a[mi][0], a[mi][1], a[mi][2], a[mi][3],
                        st + aOff[mi] + ks * 32);
            uint32_t b[8][2];
            #pragma unroll
            for (int nt = 0; nt < 4; nt++) {
                uint32_t r0, r1, r2, r3;
                ldsm_x4(r0, r1, r2, r3, st + bOff[nt] + ks * 32);
                b[nt * 2 + 0][0] = r0; b[nt * 2 + 0][1] = r1;
                b[nt * 2 + 1][0] = r2; b[nt * 2 + 1][1] = r3;
            }
            #pragma unroll
            for (int mi = 0; mi < 2; mi++)
                #pragma unroll
                for (int ni = 0; ni < 8; ni++)
                    mma_f16(acc[mi][ni], a[mi][0], a[mi][1], a[mi][2], a[mi][3],
                            b[ni][0], b[ni][1]);
        }
    }

    // ------------------- epilogue: distance + two-way mining -------------------
    const float* rsq = (const float*)(sb + OFF_RSQ);
    const int*   rlb = (const int*)(sb + OFF_RLB);
    const float* csq = (const float*)(sb + OFF_CSQ);
    const int*   clb = (const int*)(sb + OFF_CLB);

    const float INF = __int_as_float(0x7f800000);

    float apv[2][2], anv[2][2];
    float sqr[2][2]; int lbr[2][2];
    #pragma unroll
    for (int mi = 0; mi < 2; mi++)
        #pragma unroll
        for (int h = 0; h < 2; h++) {
            apv[mi][h] = 0.f;
            anv[mi][h] = INF;
            int r = wm * 32 + mi * 16 + h * 8 + (lane >> 2);
            sqr[mi][h] = rsq[r];
            lbr[mi][h] = rlb[r];
        }

    #pragma unroll
    for (int ni = 0; ni < 8; ni++) {
        const int jl = wn * 64 + ni * 8 + (lane & 3) * 2;
        float cap[2] = {0.f, 0.f};
        float can[2] = {INF, INF};
        #pragma unroll
        for (int e = 0; e < 2; e++) {
            const float sqj = csq[jl + e];
            const int   lj  = clb[jl + e];
            #pragma unroll
            for (int mi = 0; mi < 2; mi++)
                #pragma unroll
                for (int h = 0; h < 2; h++) {
                    float g = acc[mi][ni][h * 2 + e];
                    float d2 = fmaf(-2.f, g, sqr[mi][h] + sqj);
                    float dist = d2 > 0.f ? sqrtf(d2) : 0.f;
                    if (lbr[mi][h] == lj) {
                        apv[mi][h] = fmaxf(apv[mi][h], dist);
                        cap[e] = fmaxf(cap[e], dist);
                    } else {
                        anv[mi][h] = fminf(anv[mi][h], dist);
                        can[e] = fminf(can[e], dist);
                    }
                }
        }
        if (offdiag) {
            #pragma unroll
            for (int e = 0; e < 2; e++) {
                #pragma unroll
                for (int o = 4; o <= 16; o <<= 1) {
                    cap[e] = fmaxf(cap[e], __shfl_xor_sync(0xffffffffu, cap[e], o));
                    can[e] = fminf(can[e], __shfl_xor_sync(0xffffffffu, can[e], o));
                }
                if (lane < 4) {
                    int col = colBase + wn * 64 + ni * 8 + lane * 2 + e;
                    atomicMax((int*)&g_ap[col], __float_as_int(cap[e]));
                    atomicMin((int*)&g_an[col], __float_as_int(can[e]));
                }
            }
        }
    }

    #pragma unroll
    for (int mi = 0; mi < 2; mi++)
        #pragma unroll
        for (int h = 0; h < 2; h++) {
            #pragma unroll
            for (int o = 1; o <= 2; o <<= 1) {
                apv[mi][h] = fmaxf(apv[mi][h], __shfl_xor_sync(0xffffffffu, apv[mi][h], o));
                anv[mi][h] = fminf(anv[mi][h], __shfl_xor_sync(0xffffffffu, anv[mi][h], o));
            }
        }
    if ((lane & 3) == 0) {
        #pragma unroll
        for (int mi = 0; mi < 2; mi++)
            #pragma unroll
            for (int h = 0; h < 2; h++) {
                int row = rowBase + wm * 32 + mi * 16 + h * 8 + (lane >> 2);
                atomicMax((int*)&g_ap[row], __float_as_int(apv[mi][h]));
                atomicMin((int*)&g_an[row], __float_as_int(anv[mi][h]));
            }
    }

    // ------------------- fused final loss: last CTA reduces -------------------
    __syncthreads();
    __shared__ unsigned s_rank;
    if (tid == 0) {
        __threadfence();
        s_rank = atomicAdd(&g_done, 1u);
    }
    __syncthreads();
    if (s_rank == NBLK - 1) {
        __threadfence();  // make all CTAs' atomics visible
        float* ssum = (float*)(sb);            // reuse stage smem
        int*   scnt = (int*)(sb + 1024);
        float s = 0.f; int c = 0;
        for (int i = tid; i < N; i += 256) {
            float ap = g_ap[i];
            float an = g_an[i];
            if (ap > 0.f && isfinite(an)) {
                c++;
                float v = ap - an + MARGIN;
                s += v > 0.f ? v : 0.f;
            }
        }
        ssum[tid] = s;
        scnt[tid] = c;
        __syncthreads();
        for (int o = 128; o; o >>= 1) {
            if (tid < o) {
                ssum[tid] += ssum[tid + o];
                scnt[tid] += scnt[tid + o];
            }
            __syncthreads();
        }
        if (tid == 0) {
            int n = scnt[0];
            out[0] = (n > 0) ? (ssum[0] / (float)n) : 0.f;
        }
    }
}

// ---------------------------------------------------------------------------
extern "C" void kernel_launch(void* const* d_in, const int* in_sizes, int n_in,
                              void* d_out, int out_size) {
    const float* F   = (const float*)d_in[0];
    const int*   lab = (const int*)d_in[1];
    float* out = (float*)d_out;

    cudaFuncSetAttribute(mma_mine_kernel,
                         cudaFuncAttributeMaxDynamicSharedMemorySize, SMEM_BYTES);

    prep_kernel<<<N, 256>>>(F, lab);
    mma_mine_kernel<<<NBLK, 256, SMEM_BYTES>>>(out);
}

// round 11
// speedup vs baseline: 1.0888x; 1.0125x over previous
#include <cuda_runtime.h>
#include <cuda_fp16.h>
#include <math.h>
#include <stdint.h>

#define N 4096
#define D 2048
#define MARGIN 0.3f

// ---------------------------------------------------------------------------
// Device globals (no allocation allowed)
// ---------------------------------------------------------------------------
__device__ __half g_Hf[(size_t)N * D];   // fp16-rounded copy of features
__device__ float g_sq[N];
__device__ int   g_lab[N];
__device__ float g_ap[N];
__device__ float g_an[N];
__device__ unsigned g_done;              // finished-CTA ticket

// ---------------------------------------------------------------------------
// Kernel 1: round fp32 -> fp16 copy, squared norms (fp32), init accumulators
// ---------------------------------------------------------------------------
__global__ void prep_kernel(const float* __restrict__ F,
                            const int* __restrict__ lab) {
    int row = blockIdx.x;
    const float4* f4 = reinterpret_cast<const float4*>(F + (size_t)row * D);
    __half2* h2 = reinterpret_cast<__half2*>(g_Hf + (size_t)row * D);
    float s = 0.f;
    for (int k = threadIdx.x; k < D / 4; k += blockDim.x) {
        float4 v = f4[k];
        s += v.x * v.x + v.y * v.y + v.z * v.z + v.w * v.w;
        h2[k * 2 + 0] = __floats2half2_rn(v.x, v.y);
        h2[k * 2 + 1] = __floats2half2_rn(v.z, v.w);
    }
    __shared__ float red[8];
    #pragma unroll
    for (int o = 16; o; o >>= 1) s += __shfl_xor_sync(0xffffffffu, s, o);
    if ((threadIdx.x & 31) == 0) red[threadIdx.x >> 5] = s;
    __syncthreads();
    if (threadIdx.x == 0) {
        float t = 0.f;
        #pragma unroll
        for (int w = 0; w < 8; w++) t += red[w];
        g_sq[row]  = t;
        g_lab[row] = lab[row];
        g_ap[row]  = 0.f;
        g_an[row]  = __int_as_float(0x7f800000);
        if (row == 0) g_done = 0;
    }
}

// ---------------------------------------------------------------------------
// Kernel 2: fp16 mma.sync Gram tile (128x128), LOWER TRIANGLE ONLY.
// 3-stage cp.async pipeline, ONE barrier per chunk. Two-way mining.
// Last CTA to finish computes the final scalar loss (fused loss kernel).
// ---------------------------------------------------------------------------
#define TM 128
#define TN 128
#define KCH 64                       // fp16 elements per K chunk (=128B/row)
#define NCHUNK (D / KCH)             // 32
#define ROWB 144                     // padded row bytes (128 data + 16 pad)
#define TILEB (TM * ROWB)            // 18432 per tile
#define STAGEB (2 * TILEB)           // A + B per stage = 36864
#define NSTAGE 3
#define NTILE (N / TM)               // 32
#define NBLK (NTILE * (NTILE + 1) / 2)  // 528

#define OFF_RSQ (NSTAGE * STAGEB)    // float[128]
#define OFF_RLB (OFF_RSQ + 512)     // int[128]
#define OFF_CSQ (OFF_RLB + 512)     // float[128]
#define OFF_CLB (OFF_CSQ + 512)     // int[128]
#define SMEM_BYTES (OFF_CLB + 512)

__device__ __forceinline__ uint32_t smem_u32(const void* p) {
    uint32_t a;
    asm("{ .reg .u64 t; cvta.to.shared.u64 t, %1; cvt.u32.u64 %0, t; }" : "=r"(a) : "l"(p));
    return a;
}
__device__ __forceinline__ void cp16(uint32_t dst, const void* src) {
    asm volatile("cp.async.cg.shared.global [%0], [%1], 16;" :: "r"(dst), "l"(src));
}
__device__ __forceinline__ void cp_commit() {
    asm volatile("cp.async.commit_group;" ::: "memory");
}
__device__ __forceinline__ void ldsm_x4(uint32_t& r0, uint32_t& r1, uint32_t& r2,
                                        uint32_t& r3, uint32_t addr) {
    asm volatile("ldmatrix.sync.aligned.m8n8.x4.shared.b16 {%0,%1,%2,%3}, [%4];"
                 : "=r"(r0), "=r"(r1), "=r"(r2), "=r"(r3) : "r"(addr));
}
__device__ __forceinline__ void mma_f16(float* c, uint32_t a0, uint32_t a1,
                                        uint32_t a2, uint32_t a3,
                                        uint32_t b0, uint32_t b1) {
    asm volatile("mma.sync.aligned.m16n8k16.row.col.f32.f16.f16.f32 "
                 "{%0,%1,%2,%3}, {%4,%5,%6,%7}, {%8,%9}, {%0,%1,%2,%3};"
                 : "+f"(c[0]), "+f"(c[1]), "+f"(c[2]), "+f"(c[3])
                 : "r"(a0), "r"(a1), "r"(a2), "r"(a3), "r"(b0), "r"(b1));
}

__global__ __launch_bounds__(256, 2)
void mma_mine_kernel(float* __restrict__ out) {
    extern __shared__ char sb[];
    const uint32_t sbase = smem_u32(sb);
    const int tid  = threadIdx.x;
    const int lane = tid & 31;
    const int wid  = tid >> 5;
    const int wm   = wid >> 1;        // 0..3  (32 rows each)
    const int wn   = wid & 1;         // 0..1  (64 cols each)

    // decode lower-triangular tile index: bi >= bj
    int t = blockIdx.x;
    int bi = (int)floorf((sqrtf(8.0f * (float)t + 1.0f) - 1.0f) * 0.5f);
    while ((bi + 1) * (bi + 2) / 2 <= t) ++bi;
    while (bi * (bi + 1) / 2 > t) --bi;
    int bj = t - bi * (bi + 1) / 2;

    const int rowBase = bi * TM;
    const int colBase = bj * TN;
    const bool offdiag = (bi != bj);

    // stage row/col sq + labels
    if (tid < 128) {
        ((float*)(sb + OFF_RSQ))[tid] = g_sq[rowBase + tid];
        ((int*)(sb + OFF_RLB))[tid]   = g_lab[rowBase + tid];
        ((float*)(sb + OFF_CSQ))[tid] = g_sq[colBase + tid];
        ((int*)(sb + OFF_CLB))[tid]   = g_lab[colBase + tid];
    }

    // cp.async load mapping: 1024 16B vectors per tile, 4 per thread
    const int ldR = tid >> 3;         // row (with +32*i)
    const int ldQ = tid & 7;          // 16B slot within 128B row

    auto issue = [&](int c) {
        const int kc = c * KCH;
        const uint32_t st = sbase + (c % NSTAGE) * STAGEB;
        const uint32_t aB = st;
        const uint32_t bB = st + TILEB;
        #pragma unroll
        for (int i = 0; i < 4; i++) {
            int r = ldR + i * 32;
            cp16(aB + r * ROWB + ldQ * 16,
                 g_Hf + (size_t)(rowBase + r) * D + kc + ldQ * 8);
            cp16(bB + r * ROWB + ldQ * 16,
                 g_Hf + (size_t)(colBase + r) * D + kc + ldQ * 8);
        }
        cp_commit();
    };

    // ldmatrix offsets within a stage
    uint32_t aOff[2];
    #pragma unroll
    for (int mi = 0; mi < 2; mi++) {
        int r = wm * 32 + mi * 16 + (lane & 15);
        aOff[mi] = r * ROWB + (lane >> 4) * 16;
    }
    uint32_t bOff[4];
    {
        int mat = lane >> 3;
        #pragma unroll
        for (int nt = 0; nt < 4; nt++) {
            int n = wn * 64 + nt * 16 + ((mat & 2) << 2) + (lane & 7);
            bOff[nt] = TILEB + n * ROWB + (mat & 1) * 16;
        }
    }

    float acc[2][8][4];
    #pragma unroll
    for (int mi = 0; mi < 2; mi++)
        #pragma unroll
        for (int ni = 0; ni < 8; ni++)
            #pragma unroll
            for (int r = 0; r < 4; r++) acc[mi][ni][r] = 0.f;

    issue(0); issue(1);

    for (int c = 0; c < NCHUNK; c++) {
        // stage c ready? (keep at most 1 younger group in flight)
        if (c == NCHUNK - 1) asm volatile("cp.async.wait_group 0;" ::: "memory");
        else                 asm volatile("cp.async.wait_group 1;" ::: "memory");
        __syncthreads();
        // stage (c+2)%3 == (c-1)%3 is free after this barrier: refill it now
        if (c + 2 < NCHUNK) issue(c + 2);

        const uint32_t st = sbase + (c % NSTAGE) * STAGEB;
        #pragma unroll
        for (int ks = 0; ks < 4; ks++) {   // 4 x k16 = 64 k per chunk
            uint32_t a[2][4];
            #pragma unroll
            for (int mi = 0; mi < 2; mi++)
                ldsm_x4(a[mi][0], a[mi][1], a[mi][2], a[mi][3],
                        st + aOff[mi] + ks * 32);
            uint32_t b[8][2];
            #pragma unroll
            for (int nt = 0; nt < 4; nt++) {
                uint32_t r0, r1, r2, r3;
                ldsm_x4(r0, r1, r2, r3, st + bOff[nt] + ks * 32);
                b[nt * 2 + 0][0] = r0; b[nt * 2 + 0][1] = r1;
                b[nt * 2 + 1][0] = r2; b[nt * 2 + 1][1] = r3;
            }
            #pragma unroll
            for (int mi = 0; mi < 2; mi++)
                #pragma unroll
                for (int ni = 0; ni < 8; ni++)
                    mma_f16(acc[mi][ni], a[mi][0], a[mi][1], a[mi][2], a[mi][3],
                            b[ni][0], b[ni][1]);
        }
    }

    // ------------------- epilogue: distance + two-way mining -------------------
    const float* rsq = (const float*)(sb + OFF_RSQ);
    const int*   rlb = (const int*)(sb + OFF_RLB);
    const float* csq = (const float*)(sb + OFF_CSQ);
    const int*   clb = (const int*)(sb + OFF_CLB);

    const float INF = __int_as_float(0x7f800000);

    float apv[2][2], anv[2][2];
    float sqr[2][2]; int lbr[2][2];
    #pragma unroll
    for (int mi = 0; mi < 2; mi++)
        #pragma unroll
        for (int h = 0; h < 2; h++) {
            apv[mi][h] = 0.f;
            anv[mi][h] = INF;
            int r = wm * 32 + mi * 16 + h * 8 + (lane >> 2);
            sqr[mi][h] = rsq[r];
            lbr[mi][h] = rlb[r];
        }

    #pragma unroll
    for (int ni = 0; ni < 8; ni++) {
        const int jl = wn * 64 + ni * 8 + (lane & 3) * 2;
        float cap[2] = {0.f, 0.f};
        float can[2] = {INF, INF};
        #pragma unroll
        for (int e = 0; e < 2; e++) {
            const float sqj = csq[jl + e];
            const int   lj  = clb[jl + e];
            #pragma unroll
            for (int mi = 0; mi < 2; mi++)
                #pragma unroll
                for (int h = 0; h < 2; h++) {
                    float g = acc[mi][ni][h * 2 + e];
                    float d2 = fmaf(-2.f, g, sqr[mi][h] + sqj);
                    float dist = d2 > 0.f ? sqrtf(d2) : 0.f;
                    if (lbr[mi][h] == lj) {
                        apv[mi][h] = fmaxf(apv[mi][h], dist);
                        cap[e] = fmaxf(cap[e], dist);
                    } else {
                        anv[mi][h] = fminf(anv[mi][h], dist);
                        can[e] = fminf(can[e], dist);
                    }
                }
        }
        if (offdiag) {
            #pragma unroll
            for (int e = 0; e < 2; e++) {
                #pragma unroll
                for (int o = 4; o <= 16; o <<= 1) {
                    cap[e] = fmaxf(cap[e], __shfl_xor_sync(0xffffffffu, cap[e], o));
                    can[e] = fminf(can[e], __shfl_xor_sync(0xffffffffu, can[e], o));
                }
                if (lane < 4) {
                    int col = colBase + wn * 64 + ni * 8 + lane * 2 + e;
                    atomicMax((int*)&g_ap[col], __float_as_int(cap[e]));
                    atomicMin((int*)&g_an[col], __float_as_int(can[e]));
                }
            }
        }
    }

    #pragma unroll
    for (int mi = 0; mi < 2; mi++)
        #pragma unroll
        for (int h = 0; h < 2; h++) {
            #pragma unroll
            for (int o = 1; o <= 2; o <<= 1) {
                apv[mi][h] = fmaxf(apv[mi][h], __shfl_xor_sync(0xffffffffu, apv[mi][h], o));
                anv[mi][h] = fminf(anv[mi][h], __shfl_xor_sync(0xffffffffu, anv[mi][h], o));
            }
        }
    if ((lane & 3) == 0) {
        #pragma unroll
        for (int mi = 0; mi < 2; mi++)
            #pragma unroll
            for (int h = 0; h < 2; h++) {
                int row = rowBase + wm * 32 + mi * 16 + h * 8 + (lane >> 2);
                atomicMax((int*)&g_ap[row], __float_as_int(apv[mi][h]));
                atomicMin((int*)&g_an[row], __float_as_int(anv[mi][h]));
            }
    }

    // ------------------- fused final loss: last CTA reduces -------------------
    __syncthreads();
    __shared__ unsigned s_rank;
    if (tid == 0) {
        __threadfence();
        s_rank = atomicAdd(&g_done, 1u);
    }
    __syncthreads();
    if (s_rank == NBLK - 1) {
        __threadfence();  // make all CTAs' atomics visible
        float* ssum = (float*)(sb);            // reuse stage smem
        int*   scnt = (int*)(sb + 1024);
        float s = 0.f; int c = 0;
        for (int i = tid; i < N; i += 256) {
            float ap = g_ap[i];
            float an = g_an[i];
            if (ap > 0.f && isfinite(an)) {
                c++;
                float v = ap - an + MARGIN;
                s += v > 0.f ? v : 0.f;
            }
        }
        ssum[tid] = s;
        scnt[tid] = c;
        __syncthreads();
        for (int o = 128; o; o >>= 1) {
            if (tid < o) {
                ssum[tid] += ssum[tid + o];
                scnt[tid] += scnt[tid + o];
            }
            __syncthreads();
        }
        if (tid == 0) {
            int n = scnt[0];
            out[0] = (n > 0) ? (ssum[0] / (float)n) : 0.f;
        }
    }
}

// ---------------------------------------------------------------------------
extern "C" void kernel_launch(void* const* d_in, const int* in_sizes, int n_in,
                              void* d_out, int out_size) {
    const float* F   = (const float*)d_in[0];
    const int*   lab = (const int*)d_in[1];
    float* out = (float*)d_out;

    cudaFuncSetAttribute(mma_mine_kernel,
                         cudaFuncAttributeMaxDynamicSharedMemorySize, SMEM_BYTES);

    prep_kernel<<<N, 256>>>(F, lab);
    mma_mine_kernel<<<NBLK, 256, SMEM_BYTES>>>(out);
}

// round 12
// speedup vs baseline: 1.2401x; 1.1390x over previous
#include <cuda_runtime.h>
#include <cuda_fp16.h>
#include <math.h>
#include <stdint.h>

#define N 4096
#define D 2048
#define MARGIN 0.3f

// ---------------------------------------------------------------------------
// Device globals (no allocation allowed)
// ---------------------------------------------------------------------------
__device__ __half g_Hf[(size_t)N * D];   // fp16-rounded copy of features
__device__ float g_sq[N];
__device__ int   g_lab[N];
__device__ float g_ap[N];
__device__ float g_an[N];
__device__ unsigned g_done;              // finished-CTA ticket

// ---------------------------------------------------------------------------
// Kernel 1: round fp32 -> fp16 copy, squared norms (fp32), init accumulators
// ---------------------------------------------------------------------------
__global__ void prep_kernel(const float* __restrict__ F,
                            const int* __restrict__ lab) {
    int row = blockIdx.x;
    const float4* f4 = reinterpret_cast<const float4*>(F + (size_t)row * D);
    __half2* h2 = reinterpret_cast<__half2*>(g_Hf + (size_t)row * D);
    float s = 0.f;
    for (int k = threadIdx.x; k < D / 4; k += blockDim.x) {
        float4 v = f4[k];
        s += v.x * v.x + v.y * v.y + v.z * v.z + v.w * v.w;
        h2[k * 2 + 0] = __floats2half2_rn(v.x, v.y);
        h2[k * 2 + 1] = __floats2half2_rn(v.z, v.w);
    }
    __shared__ float red[8];
    #pragma unroll
    for (int o = 16; o; o >>= 1) s += __shfl_xor_sync(0xffffffffu, s, o);
    if ((threadIdx.x & 31) == 0) red[threadIdx.x >> 5] = s;
    __syncthreads();
    if (threadIdx.x == 0) {
        float t = 0.f;
        #pragma unroll
        for (int w = 0; w < 8; w++) t += red[w];
        g_sq[row]  = t;
        g_lab[row] = lab[row];
        g_ap[row]  = 0.f;
        g_an[row]  = __int_as_float(0x7f800000);
        if (row == 0) g_done = 0;
    }
}

// ---------------------------------------------------------------------------
// Kernel 2: fp16 mma.sync Gram tile 64x128, 128 threads, 4 CTAs/SM.
// Tile set {bi >= 2*bj} covers the lower triangle; all tiles mine both ways.
// Last CTA to finish computes the final scalar loss.
// ---------------------------------------------------------------------------
#define TM 64
#define TN 128
#define KCH 64                        // fp16 elements per K chunk (=128B/row)
#define NCHUNK (D / KCH)              // 32
#define ROWB 144                      // padded row bytes (128 data + 16 pad)
#define A_BYTES (TM * ROWB)           // 9216
#define B_BYTES (TN * ROWB)           // 18432
#define STAGEB (A_BYTES + B_BYTES)    // 27648
#define NSTAGE 2
#define NBLK 1056                     // sum_{bj=0}^{31} (64 - 2*bj)

#define OFF_RSQ (NSTAGE * STAGEB)     // float[64]
#define OFF_RLB (OFF_RSQ + 256)      // int[64]
#define OFF_CSQ (OFF_RLB + 256)      // float[128]
#define OFF_CLB (OFF_CSQ + 512)      // int[128]
#define SMEM_BYTES (OFF_CLB + 512)    // 56832

__device__ __forceinline__ uint32_t smem_u32(const void* p) {
    uint32_t a;
    asm("{ .reg .u64 t; cvta.to.shared.u64 t, %1; cvt.u32.u64 %0, t; }" : "=r"(a) : "l"(p));
    return a;
}
__device__ __forceinline__ void cp16(uint32_t dst, const void* src) {
    asm volatile("cp.async.cg.shared.global [%0], [%1], 16;" :: "r"(dst), "l"(src));
}
__device__ __forceinline__ void cp_commit() {
    asm volatile("cp.async.commit_group;" ::: "memory");
}
__device__ __forceinline__ void ldsm_x4(uint32_t& r0, uint32_t& r1, uint32_t& r2,
                                        uint32_t& r3, uint32_t addr) {
    asm volatile("ldmatrix.sync.aligned.m8n8.x4.shared.b16 {%0,%1,%2,%3}, [%4];"
                 : "=r"(r0), "=r"(r1), "=r"(r2), "=r"(r3) : "r"(addr));
}
__device__ __forceinline__ void mma_f16(float* c, uint32_t a0, uint32_t a1,
                                        uint32_t a2, uint32_t a3,
                                        uint32_t b0, uint32_t b1) {
    asm volatile("mma.sync.aligned.m16n8k16.row.col.f32.f16.f16.f32 "
                 "{%0,%1,%2,%3}, {%4,%5,%6,%7}, {%8,%9}, {%0,%1,%2,%3};"
                 : "+f"(c[0]), "+f"(c[1]), "+f"(c[2]), "+f"(c[3])
                 : "r"(a0), "r"(a1), "r"(a2), "r"(a3), "r"(b0), "r"(b1));
}

__global__ __launch_bounds__(128, 4)
void mma_mine_kernel(float* __restrict__ out) {
    extern __shared__ char sb[];
    const uint32_t sbase = smem_u32(sb);
    const int tid  = threadIdx.x;
    const int lane = tid & 31;
    const int wid  = tid >> 5;
    const int wm   = wid >> 1;        // 0..1  (32 rows each)
    const int wn   = wid & 1;         // 0..1  (64 cols each)

    // decode tile index over {bi >= 2*bj}: bj has (64 - 2*bj) row-tiles
    int t = blockIdx.x;
    int bj = 0, s = 0;
    while (s + (64 - 2 * bj) <= t) { s += 64 - 2 * bj; bj++; }
    int bi = 2 * bj + (t - s);

    const int rowBase = bi * TM;
    const int colBase = bj * TN;

    // stage row/col sq + labels
    if (tid < 64) {
        ((float*)(sb + OFF_RSQ))[tid] = g_sq[rowBase + tid];
        ((int*)(sb + OFF_RLB))[tid]   = g_lab[rowBase + tid];
    }
    ((float*)(sb + OFF_CSQ))[tid] = g_sq[colBase + tid];
    ((int*)(sb + OFF_CLB))[tid]   = g_lab[colBase + tid];

    // cp.async: A 512 vecs (4/thread), B 1024 vecs (8/thread)
    const int ldR = tid >> 3;         // 0..15 (+16*i)
    const int ldQ = tid & 7;          // 16B slot within 128B row

    auto issue = [&](int c) {
        const int kc = c * KCH;
        const uint32_t st = sbase + (c & 1) * STAGEB;
        const uint32_t aB = st;
        const uint32_t bB = st + A_BYTES;
        #pragma unroll
        for (int i = 0; i < 4; i++) {
            int r = ldR + i * 16;
            cp16(aB + r * ROWB + ldQ * 16,
                 g_Hf + (size_t)(rowBase + r) * D + kc + ldQ * 8);
        }
        #pragma unroll
        for (int i = 0; i < 8; i++) {
            int r = ldR + i * 16;
            cp16(bB + r * ROWB + ldQ * 16,
                 g_Hf + (size_t)(colBase + r) * D + kc + ldQ * 8);
        }
        cp_commit();
    };

    // ldmatrix offsets within a stage
    uint32_t aOff[2];
    #pragma unroll
    for (int mi = 0; mi < 2; mi++) {
        int r = wm * 32 + mi * 16 + (lane & 15);
        aOff[mi] = r * ROWB + (lane >> 4) * 16;
    }
    uint32_t bOff[4];
    {
        int mat = lane >> 3;
        #pragma unroll
        for (int nt = 0; nt < 4; nt++) {
            int n = wn * 64 + nt * 16 + ((mat & 2) << 2) + (lane & 7);
            bOff[nt] = A_BYTES + n * ROWB + (mat & 1) * 16;
        }
    }

    float acc[2][8][4];
    #pragma unroll
    for (int mi = 0; mi < 2; mi++)
        #pragma unroll
        for (int ni = 0; ni < 8; ni++)
            #pragma unroll
            for (int r = 0; r < 4; r++) acc[mi][ni][r] = 0.f;

    issue(0);

    for (int c = 0; c < NCHUNK; c++) {
        if (c + 1 < NCHUNK) {
            issue(c + 1);
            asm volatile("cp.async.wait_group 1;" ::: "memory");
        } else {
            asm volatile("cp.async.wait_group 0;" ::: "memory");
        }
        __syncthreads();

        const uint32_t st = sbase + (c & 1) * STAGEB;
        #pragma unroll
        for (int ks = 0; ks < 4; ks++) {   // 4 x k16 = 64 k per chunk
            uint32_t a[2][4];
            #pragma unroll
            for (int mi = 0; mi < 2; mi++)
                ldsm_x4(a[mi][0], a[mi][1], a[mi][2], a[mi][3],
                        st + aOff[mi] + ks * 32);
            uint32_t b[8][2];
            #pragma unroll
            for (int nt = 0; nt < 4; nt++) {
                uint32_t r0, r1, r2, r3;
                ldsm_x4(r0, r1, r2, r3, st + bOff[nt] + ks * 32);
                b[nt * 2 + 0][0] = r0; b[nt * 2 + 0][1] = r1;
                b[nt * 2 + 1][0] = r2; b[nt * 2 + 1][1] = r3;
            }
            #pragma unroll
            for (int mi = 0; mi < 2; mi++)
                #pragma unroll
                for (int ni = 0; ni < 8; ni++)
                    mma_f16(acc[mi][ni], a[mi][0], a[mi][1], a[mi][2], a[mi][3],
                            b[ni][0], b[ni][1]);
        }
        __syncthreads();
    }

    // ------------------- epilogue: distance + two-way mining -------------------
    const float* rsq = (const float*)(sb + OFF_RSQ);
    const int*   rlb = (const int*)(sb + OFF_RLB);
    const float* csq = (const float*)(sb + OFF_CSQ);
    const int*   clb = (const int*)(sb + OFF_CLB);

    const float INF = __int_as_float(0x7f800000);

    float apv[2][2], anv[2][2];
    float sqr[2][2]; int lbr[2][2];
    #pragma unroll
    for (int mi = 0; mi < 2; mi++)
        #pragma unroll
        for (int h = 0; h < 2; h++) {
            apv[mi][h] = 0.f;
            anv[mi][h] = INF;
            int r = wm * 32 + mi * 16 + h * 8 + (lane >> 2);
            sqr[mi][h] = rsq[r];
            lbr[mi][h] = rlb[r];
        }

    #pragma unroll
    for (int ni = 0; ni < 8; ni++) {
        const int jl = wn * 64 + ni * 8 + (lane & 3) * 2;
        float cap[2] = {0.f, 0.f};
        float can[2] = {INF, INF};
        #pragma unroll
        for (int e = 0; e < 2; e++) {
            const float sqj = csq[jl + e];
            const int   lj  = clb[jl + e];
            #pragma unroll
            for (int mi = 0; mi < 2; mi++)
                #pragma unroll
                for (int h = 0; h < 2; h++) {
                    float g = acc[mi][ni][h * 2 + e];
                    float d2 = fmaf(-2.f, g, sqr[mi][h] + sqj);
                    float dist = d2 > 0.f ? sqrtf(d2) : 0.f;
                    if (lbr[mi][h] == lj) {
                        apv[mi][h] = fmaxf(apv[mi][h], dist);
                        cap[e] = fmaxf(cap[e], dist);
                    } else {
                        anv[mi][h] = fminf(anv[mi][h], dist);
                        can[e] = fminf(can[e], dist);
                    }
                }
        }
        // column mining (all tiles; mirrored extras are idempotent)
        #pragma unroll
        for (int e = 0; e < 2; e++) {
            #pragma unroll
            for (int o = 4; o <= 16; o <<= 1) {
                cap[e] = fmaxf(cap[e], __shfl_xor_sync(0xffffffffu, cap[e], o));
                can[e] = fminf(can[e], __shfl_xor_sync(0xffffffffu, can[e], o));
            }
            if (lane < 4) {
                int col = colBase + wn * 64 + ni * 8 + lane * 2 + e;
                atomicMax((int*)&g_ap[col], __float_as_int(cap[e]));
                atomicMin((int*)&g_an[col], __float_as_int(can[e]));
            }
        }
    }

    // row-side reduction over 4 lanes sharing each row
    #pragma unroll
    for (int mi = 0; mi < 2; mi++)
        #pragma unroll
        for (int h = 0; h < 2; h++) {
            #pragma unroll
            for (int o = 1; o <= 2; o <<= 1) {
                apv[mi][h] = fmaxf(apv[mi][h], __shfl_xor_sync(0xffffffffu, apv[mi][h], o));
                anv[mi][h] = fminf(anv[mi][h], __shfl_xor_sync(0xffffffffu, anv[mi][h], o));
            }
        }
    if ((lane & 3) == 0) {
        #pragma unroll
        for (int mi = 0; mi < 2; mi++)
            #pragma unroll
            for (int h = 0; h < 2; h++) {
                int row = rowBase + wm * 32 + mi * 16 + h * 8 + (lane >> 2);
                atomicMax((int*)&g_ap[row], __float_as_int(apv[mi][h]));
                atomicMin((int*)&g_an[row], __float_as_int(anv[mi][h]));
            }
    }

    // ------------------- fused final loss: last CTA reduces -------------------
    __syncthreads();
    __shared__ unsigned s_rank;
    if (tid == 0) {
        __threadfence();
        s_rank = atomicAdd(&g_done, 1u);
    }
    __syncthreads();
    if (s_rank == NBLK - 1) {
        __threadfence();  // make all CTAs' atomics visible
        float* ssum = (float*)(sb);            // reuse stage smem
        int*   scnt = (int*)(sb + 1024);
        float s2 = 0.f; int c = 0;
        for (int i = tid; i < N; i += 128) {
            float ap = g_ap[i];
            float an = g_an[i];
            if (ap > 0.f && isfinite(an)) {
                c++;
                float v = ap - an + MARGIN;
                s2 += v > 0.f ? v : 0.f;
            }
        }
        ssum[tid] = s2;
        scnt[tid] = c;
        __syncthreads();
        for (int o = 64; o; o >>= 1) {
            if (tid < o) {
                ssum[tid] += ssum[tid + o];
                scnt[tid] += scnt[tid + o];
            }
            __syncthreads();
        }
        if (tid == 0) {
            int n = scnt[0];
            out[0] = (n > 0) ? (ssum[0] / (float)n) : 0.f;
        }
    }
}

// ---------------------------------------------------------------------------
extern "C" void kernel_launch(void* const* d_in, const int* in_sizes, int n_in,
                              void* d_out, int out_size) {
    const float* F   = (const float*)d_in[0];
    const int*   lab = (const int*)d_in[1];
    float* out = (float*)d_out;

    cudaFuncSetAttribute(mma_mine_kernel,
                         cudaFuncAttributeMaxDynamicSharedMemorySize, SMEM_BYTES);

    prep_kernel<<<N, 256>>>(F, lab);
    mma_mine_kernel<<<NBLK, 128, SMEM_BYTES>>>(out);
}

// round 13
// speedup vs baseline: 1.2985x; 1.0471x over previous
#include <cuda_runtime.h>
#include <cuda_fp16.h>
#include <math.h>
#include <stdint.h>

#define N 4096
#define D 2048
#define MARGIN 0.3f

// ---------------------------------------------------------------------------
// Device globals (no allocation allowed)
// ---------------------------------------------------------------------------
__device__ __half g_Hf[(size_t)N * D];   // fp16-rounded copy of features
__device__ float g_sq[N];
__device__ int   g_lab[N];
__device__ float g_ap[N];
__device__ float g_an[N];
__device__ unsigned g_done;              // finished-CTA ticket

// ---------------------------------------------------------------------------
// Kernel 1 (v2): warp-per-row. 512 CTAs x 8 warps = 4096 rows.
// Each lane: 16 float4 loads (MLP 16), convert to fp16, warp-reduce norm.
// ---------------------------------------------------------------------------
__global__ __launch_bounds__(256)
void prep_kernel(const float* __restrict__ F,
                 const int* __restrict__ lab) {
    const int row  = blockIdx.x * 8 + (threadIdx.x >> 5);
    const int lane = threadIdx.x & 31;
    const float4* f4 = reinterpret_cast<const float4*>(F + (size_t)row * D);
    __half2* h2 = reinterpret_cast<__half2*>(g_Hf + (size_t)row * D);
    float s = 0.f;
    #pragma unroll
    for (int i = 0; i < 16; i++) {
        int k = lane + i * 32;
        float4 v = f4[k];
        s += v.x * v.x + v.y * v.y + v.z * v.z + v.w * v.w;
        h2[k * 2 + 0] = __floats2half2_rn(v.x, v.y);
        h2[k * 2 + 1] = __floats2half2_rn(v.z, v.w);
    }
    #pragma unroll
    for (int o = 16; o; o >>= 1) s += __shfl_xor_sync(0xffffffffu, s, o);
    if (lane == 0) {
        g_sq[row]  = s;
        g_lab[row] = lab[row];
        g_ap[row]  = 0.f;
        g_an[row]  = __int_as_float(0x7f800000);
        if (row == 0) g_done = 0;
    }
}

// ---------------------------------------------------------------------------
// Kernel 2: fp16 mma.sync Gram tile 64x128, 128 threads, 3 CTAs/SM,
// ks-level fragment double-buffering. Tile set {bi >= 2*bj}; two-way mining.
// Last CTA to finish computes the final scalar loss.
// ---------------------------------------------------------------------------
#define TM 64
#define TN 128
#define KCH 64                        // fp16 elements per K chunk (=128B/row)
#define NCHUNK (D / KCH)              // 32
#define ROWB 144                      // padded row bytes (128 data + 16 pad)
#define A_BYTES (TM * ROWB)           // 9216
#define B_BYTES (TN * ROWB)           // 18432
#define STAGEB (A_BYTES + B_BYTES)    // 27648
#define NBLK 1056                     // sum_{bj=0}^{31} (64 - 2*bj)

#define OFF_RSQ (2 * STAGEB)          // float[64]
#define OFF_RLB (OFF_RSQ + 256)      // int[64]
#define OFF_CSQ (OFF_RLB + 256)      // float[128]
#define OFF_CLB (OFF_CSQ + 512)      // int[128]
#define SMEM_BYTES (OFF_CLB + 512)    // 56832

__device__ __forceinline__ uint32_t smem_u32(const void* p) {
    uint32_t a;
    asm("{ .reg .u64 t; cvta.to.shared.u64 t, %1; cvt.u32.u64 %0, t; }" : "=r"(a) : "l"(p));
    return a;
}
__device__ __forceinline__ void cp16(uint32_t dst, const void* src) {
    asm volatile("cp.async.cg.shared.global [%0], [%1], 16;" :: "r"(dst), "l"(src));
}
__device__ __forceinline__ void cp_commit() {
    asm volatile("cp.async.commit_group;" ::: "memory");
}
__device__ __forceinline__ void ldsm_x4(uint32_t& r0, uint32_t& r1, uint32_t& r2,
                                        uint32_t& r3, uint32_t addr) {
    asm volatile("ldmatrix.sync.aligned.m8n8.x4.shared.b16 {%0,%1,%2,%3}, [%4];"
                 : "=r"(r0), "=r"(r1), "=r"(r2), "=r"(r3) : "r"(addr));
}
__device__ __forceinline__ void mma_f16(float* c, uint32_t a0, uint32_t a1,
                                        uint32_t a2, uint32_t a3,
                                        uint32_t b0, uint32_t b1) {
    asm volatile("mma.sync.aligned.m16n8k16.row.col.f32.f16.f16.f32 "
                 "{%0,%1,%2,%3}, {%4,%5,%6,%7}, {%8,%9}, {%0,%1,%2,%3};"
                 : "+f"(c[0]), "+f"(c[1]), "+f"(c[2]), "+f"(c[3])
                 : "r"(a0), "r"(a1), "r"(a2), "r"(a3), "r"(b0), "r"(b1));
}

__global__ __launch_bounds__(128, 3)
void mma_mine_kernel(float* __restrict__ out) {
    extern __shared__ char sb[];
    const uint32_t sbase = smem_u32(sb);
    const int tid  = threadIdx.x;
    const int lane = tid & 31;
    const int wid  = tid >> 5;
    const int wm   = wid >> 1;        // 0..1  (32 rows each)
    const int wn   = wid & 1;         // 0..1  (64 cols each)

    // decode tile index over {bi >= 2*bj}: bj has (64 - 2*bj) row-tiles
    int t = blockIdx.x;
    int bj = 0, s = 0;
    while (s + (64 - 2 * bj) <= t) { s += 64 - 2 * bj; bj++; }
    int bi = 2 * bj + (t - s);

    const int rowBase = bi * TM;
    const int colBase = bj * TN;

    // stage row/col sq + labels
    if (tid < 64) {
        ((float*)(sb + OFF_RSQ))[tid] = g_sq[rowBase + tid];
        ((int*)(sb + OFF_RLB))[tid]   = g_lab[rowBase + tid];
    }
    ((float*)(sb + OFF_CSQ))[tid] = g_sq[colBase + tid];
    ((int*)(sb + OFF_CLB))[tid]   = g_lab[colBase + tid];

    // cp.async: A 512 vecs (4/thread), B 1024 vecs (8/thread)
    const int ldR = tid >> 3;         // 0..15 (+16*i)
    const int ldQ = tid & 7;          // 16B slot within 128B row

    auto issue = [&](int c) {
        const int kc = c * KCH;
        const uint32_t st = sbase + (c & 1) * STAGEB;
        const uint32_t aB = st;
        const uint32_t bB = st + A_BYTES;
        #pragma unroll
        for (int i = 0; i < 4; i++) {
            int r = ldR + i * 16;
            cp16(aB + r * ROWB + ldQ * 16,
                 g_Hf + (size_t)(rowBase + r) * D + kc + ldQ * 8);
        }
        #pragma unroll
        for (int i = 0; i < 8; i++) {
            int r = ldR + i * 16;
            cp16(bB + r * ROWB + ldQ * 16,
                 g_Hf + (size_t)(colBase + r) * D + kc + ldQ * 8);
        }
        cp_commit();
    };

    // ldmatrix offsets within a stage
    uint32_t aOff[2];
    #pragma unroll
    for (int mi = 0; mi < 2; mi++) {
        int r = wm * 32 + mi * 16 + (lane & 15);
        aOff[mi] = r * ROWB + (lane >> 4) * 16;
    }
    uint32_t bOff[4];
    {
        int mat = lane >> 3;
        #pragma unroll
        for (int nt = 0; nt < 4; nt++) {
            int n = wn * 64 + nt * 16 + ((mat & 2) << 2) + (lane & 7);
            bOff[nt] = A_BYTES + n * ROWB + (mat & 1) * 16;
        }
    }

    float acc[2][8][4];
    #pragma unroll
    for (int mi = 0; mi < 2; mi++)
        #pragma unroll
        for (int ni = 0; ni < 8; ni++)
            #pragma unroll
            for (int r = 0; r < 4; r++) acc[mi][ni][r] = 0.f;

    // double-buffered fragments (parity = ks & 1)
    uint32_t fa[2][2][4];
    uint32_t fb[2][8][2];

    auto ldfrag = [&](int par, uint32_t st, int ks) {
        #pragma unroll
        for (int mi = 0; mi < 2; mi++)
            ldsm_x4(fa[par][mi][0], fa[par][mi][1], fa[par][mi][2], fa[par][mi][3],
                    st + aOff[mi] + ks * 32);
        #pragma unroll
        for (int nt = 0; nt < 4; nt++) {
            uint32_t r0, r1, r2, r3;
            ldsm_x4(r0, r1, r2, r3, st + bOff[nt] + ks * 32);
            fb[par][nt * 2 + 0][0] = r0; fb[par][nt * 2 + 0][1] = r1;
            fb[par][nt * 2 + 1][0] = r2; fb[par][nt * 2 + 1][1] = r3;
        }
    };
    auto domma = [&](int par) {
        #pragma unroll
        for (int mi = 0; mi < 2; mi++)
            #pragma unroll
            for (int ni = 0; ni < 8; ni++)
                mma_f16(acc[mi][ni],
                        fa[par][mi][0], fa[par][mi][1], fa[par][mi][2], fa[par][mi][3],
                        fb[par][ni][0], fb[par][ni][1]);
    };

    issue(0); issue(1);
    asm volatile("cp.async.wait_group 1;" ::: "memory");
    __syncthreads();                      // stage 0 visible to all warps
    ldfrag(0, sbase, 0);

    for (int c = 0; c < NCHUNK; c++) {
        const uint32_t st = sbase + (c & 1) * STAGEB;
        #pragma unroll
        for (int ks = 0; ks < 4; ks++) {
            if (ks < 3) ldfrag((ks + 1) & 1, st, ks + 1);
            domma(ks & 1);
        }
        __syncthreads();                  // all warps done reading stage c
        if (c + 1 < NCHUNK) {
            if (c + 2 < NCHUNK) {
                issue(c + 2);
                asm volatile("cp.async.wait_group 1;" ::: "memory");
            } else {
                asm volatile("cp.async.wait_group 0;" ::: "memory");
            }
            __syncthreads();              // publish stage c+1
            ldfrag(0, sbase + ((c + 1) & 1) * STAGEB, 0);
        }
    }

    // ------------------- epilogue: distance + two-way mining -------------------
    const float* rsq = (const float*)(sb + OFF_RSQ);
    const int*   rlb = (const int*)(sb + OFF_RLB);
    const float* csq = (const float*)(sb + OFF_CSQ);
    const int*   clb = (const int*)(sb + OFF_CLB);

    const float INF = __int_as_float(0x7f800000);

    float apv[2][2], anv[2][2];
    float sqr[2][2]; int lbr[2][2];
    #pragma unroll
    for (int mi = 0; mi < 2; mi++)
        #pragma unroll
        for (int h = 0; h < 2; h++) {
            apv[mi][h] = 0.f;
            anv[mi][h] = INF;
            int r = wm * 32 + mi * 16 + h * 8 + (lane >> 2);
            sqr[mi][h] = rsq[r];
            lbr[mi][h] = rlb[r];
        }

    #pragma unroll
    for (int ni = 0; ni < 8; ni++) {
        const int jl = wn * 64 + ni * 8 + (lane & 3) * 2;
        float cap[2] = {0.f, 0.f};
        float can[2] = {INF, INF};
        #pragma unroll
        for (int e = 0; e < 2; e++) {
            const float sqj = csq[jl + e];
            const int   lj  = clb[jl + e];
            #pragma unroll
            for (int mi = 0; mi < 2; mi++)
                #pragma unroll
                for (int h = 0; h < 2; h++) {
                    float g = acc[mi][ni][h * 2 + e];
                    float d2 = fmaf(-2.f, g, sqr[mi][h] + sqj);
                    float dist = d2 > 0.f ? sqrtf(d2) : 0.f;
                    if (lbr[mi][h] == lj) {
                        apv[mi][h] = fmaxf(apv[mi][h], dist);
                        cap[e] = fmaxf(cap[e], dist);
                    } else {
                        anv[mi][h] = fminf(anv[mi][h], dist);
                        can[e] = fminf(can[e], dist);
                    }
                }
        }
        // column mining (mirrored extras are idempotent for max/min)
        #pragma unroll
        for (int e = 0; e < 2; e++) {
            #pragma unroll
            for (int o = 4; o <= 16; o <<= 1) {
                cap[e] = fmaxf(cap[e], __shfl_xor_sync(0xffffffffu, cap[e], o));
                can[e] = fminf(can[e], __shfl_xor_sync(0xffffffffu, can[e], o));
            }
            if (lane < 4) {
                int col = colBase + wn * 64 + ni * 8 + lane * 2 + e;
                atomicMax((int*)&g_ap[col], __float_as_int(cap[e]));
                atomicMin((int*)&g_an[col], __float_as_int(can[e]));
            }
        }
    }

    // row-side reduction over 4 lanes sharing each row
    #pragma unroll
    for (int mi = 0; mi < 2; mi++)
        #pragma unroll
        for (int h = 0; h < 2; h++) {
            #pragma unroll
            for (int o = 1; o <= 2; o <<= 1) {
                apv[mi][h] = fmaxf(apv[mi][h], __shfl_xor_sync(0xffffffffu, apv[mi][h], o));
                anv[mi][h] = fminf(anv[mi][h], __shfl_xor_sync(0xffffffffu, anv[mi][h], o));
            }
        }
    if ((lane & 3) == 0) {
        #pragma unroll
        for (int mi = 0; mi < 2; mi++)
            #pragma unroll
            for (int h = 0; h < 2; h++) {
                int row = rowBase + wm * 32 + mi * 16 + h * 8 + (lane >> 2);
                atomicMax((int*)&g_ap[row], __float_as_int(apv[mi][h]));
                atomicMin((int*)&g_an[row], __float_as_int(anv[mi][h]));
            }
    }

    // ------------------- fused final loss: last CTA reduces -------------------
    __syncthreads();
    __shared__ unsigned s_rank;
    if (tid == 0) {
        __threadfence();
        s_rank = atomicAdd(&g_done, 1u);
    }
    __syncthreads();
    if (s_rank == NBLK - 1) {
        __threadfence();  // make all CTAs' atomics visible
        float* ssum = (float*)(sb);            // reuse stage smem
        int*   scnt = (int*)(sb + 1024);
        float s2 = 0.f; int c = 0;
        for (int i = tid; i < N; i += 128) {
            float ap = g_ap[i];
            float an = g_an[i];
            if (ap > 0.f && isfinite(an)) {
                c++;
                float v = ap - an + MARGIN;
                s2 += v > 0.f ? v : 0.f;
            }
        }
        ssum[tid] = s2;
        scnt[tid] = c;
        __syncthreads();
        for (int o = 64; o; o >>= 1) {
            if (tid < o) {
                ssum[tid] += ssum[tid + o];
                scnt[tid] += scnt[tid + o];
            }
            __syncthreads();
        }
        if (tid == 0) {
            int n = scnt[0];
            out[0] = (n > 0) ? (ssum[0] / (float)n) : 0.f;
        }
    }
}

// ---------------------------------------------------------------------------
extern "C" void kernel_launch(void* const* d_in, const int* in_sizes, int n_in,
                              void* d_out, int out_size) {
    const float* F   = (const float*)d_in[0];
    const int*   lab = (const int*)d_in[1];
    float* out = (float*)d_out;

    cudaFuncSetAttribute(mma_mine_kernel,
                         cudaFuncAttributeMaxDynamicSharedMemorySize, SMEM_BYTES);

    prep_kernel<<<N / 8, 256>>>(F, lab);
    mma_mine_kernel<<<NBLK, 128, SMEM_BYTES>>>(out);
}